// round 15
// baseline (speedup 1.0000x reference)
#include <cuda_runtime.h>
#include <cuda.h>
#include <cuda_fp16.h>
#include <cstdint>

// Problem dims (fixed by reference)
#define BB 16
#define TT 4096
#define DD 512           // K dim of GEMM / feature dim
#define EE 512           // N dim of GEMM
#define MTOT (BB*TT)     // 65536 rows

// Mixed tile schedule: batches 0-12 -> 128-row tiles, batches 13-15 -> 64-row.
#define N_BIG   416      // 13 batches x 32 tiles
#define N_SMALL 192      // 3 batches x 64 tiles
#define NCTAS   (N_BIG + N_SMALL)   // 608
#define SPLIT_ROW (N_BIG * 128)     // 53248 = start of small-tile region

// ---------------- scratch (device globals; no allocation) ----------------
__device__ __align__(16) __half g_Whf[EE * DD];    // transposed W fp16: Whf[e][d]
__device__ __align__(16) float g_part[NCTAS * DD]; // per-CTA partial weighted sums
__device__ __align__(16) float g_pmax[NCTAS];      // per-CTA score max
__device__ __align__(16) float g_psum[NCTAS];      // per-CTA sum exp(score-max)
__device__ unsigned g_wdone;  // transpose arrival counter; NEVER reset (replay-safe)

// ---------------- PTX helpers ----------------
__device__ __forceinline__ uint32_t smem_u32(const void* p) {
    uint32_t a;
    asm("{ .reg .u64 t; cvta.to.shared.u64 t, %1; cvt.u32.u64 %0, t; }" : "=r"(a) : "l"(p));
    return a;
}

#define MBARRIER_INIT(addr, cnt) \
    asm volatile("mbarrier.init.shared.b64 [%0], %1;" :: "r"((uint32_t)(addr)), "r"((uint32_t)(cnt)) : "memory")

#define MBARRIER_EXPECT_TX(addr, bytes) \
    asm volatile("mbarrier.arrive.expect_tx.shared.b64 _, [%0], %1;" :: "r"((uint32_t)(addr)), "r"((uint32_t)(bytes)) : "memory")

#define MBARRIER_WAIT_PARITY(mbar_smem_addr, phase_parity) do { \
    uint32_t _mbar = (uint32_t)(mbar_smem_addr); \
    uint32_t _parity = (uint32_t)(phase_parity); \
    uint32_t _done; \
    asm volatile( \
        "{\n\t" \
        ".reg .pred p;\n\t" \
        "mbarrier.try_wait.parity.acquire.cta.shared::cta.b64 p, [%1], %2;\n\t" \
        "selp.b32 %0, 1, 0, p;\n\t" \
        "}" \
        : "=r"(_done) : "r"(_mbar), "r"(_parity) : "memory"); \
    if (!_done) { \
        asm volatile( \
            "{\n\t" \
            ".reg .pred P1;\n\t" \
            "WAIT_LOOP_%=:\n\t" \
            "mbarrier.try_wait.parity.acquire.cta.shared::cta.b64 P1, [%0], %1, 0x989680;\n\t" \
            "@P1 bra.uni WAIT_DONE_%=;\n\t" \
            "bra.uni WAIT_LOOP_%=;\n\t" \
            "WAIT_DONE_%=:\n\t" \
            "}" \
            :: "r"(_mbar), "r"(_parity) : "memory"); \
    } \
} while(0)

#define TMA_LOAD_2D(smem_addr, map_ptr, c0, c1, mbar) \
    asm volatile("cp.async.bulk.tensor.2d.shared::cta.global.tile.mbarrier::complete_tx::bytes " \
        "[%0], [%1, {%2, %3}], [%4];" \
        :: "r"((uint32_t)(smem_addr)), "l"(map_ptr), "r"((int)(c0)), "r"((int)(c1)), \
           "r"((uint32_t)(mbar)) : "memory")

#define FENCE_PROXY_ASYNC() asm volatile("fence.proxy.async;" ::: "memory")

__device__ __forceinline__ void ldsm_x4(uint32_t* r, uint32_t addr) {
    asm volatile("ldmatrix.sync.aligned.m8n8.x4.shared.b16 {%0,%1,%2,%3}, [%4];"
        : "=r"(r[0]), "=r"(r[1]), "=r"(r[2]), "=r"(r[3]) : "r"(addr));
}
// fp16 inputs, fp32 accumulate
__device__ __forceinline__ void mma_f16f32(float* d, const uint32_t* a, const uint32_t* b) {
    asm volatile("mma.sync.aligned.m16n8k16.row.col.f32.f16.f16.f32 "
        "{%0,%1,%2,%3}, {%4,%5,%6,%7}, {%8,%9}, {%0,%1,%2,%3};"
        : "+f"(d[0]), "+f"(d[1]), "+f"(d[2]), "+f"(d[3])
        : "r"(a[0]), "r"(a[1]), "r"(a[2]), "r"(a[3]), "r"(b[0]), "r"(b[1]));
}
__device__ __forceinline__ float tanh_approx(float x) {
    float r;
    asm("tanh.approx.f32 %0, %1;" : "=f"(r) : "f"(x));
    return r;
}

// ---------------- kernel 1: transpose(W) + GEMM + tanh + dot(v) + pool ------
// Tile paths (R13-proven):
//   big  (bid < 416): 128 rows, 8 warps m16xn32
//   small(bid >= 416): 64 rows, 8 warps 4(m)x2(n) m16xn16
// W transpose folded in: CTAs 0-63 each transpose one 64x64 tile of W into
// g_Whf (before their A-load; smem A region as scratch), fence.proxy.async +
// threadfence, then bump g_wdone. EVERY CTA spins on g_wdone>=64 (acquire)
// after its A-load, before issuing W TMA — no SM-count/residency assumption
// (R14 failed because GB300 has 152 SMs, not 148: 4 wave-1 CTAs raced the
// transpose). Late CTAs pass the spin instantly. g_wdone never resets:
// replays pass instantly; re-transposition writes identical bytes.
#define N_CHUNK  32
#define N_CHUNKS 16
#define W_CHUNK_BYTES 32768   // 32 n-rows x 512 k x 2B

// smem offsets
#define SM_FULL   0           // 2 full mbarriers
#define SM_V      64          // 512 floats -> 2112
#define SM_SC     2112        // 128 floats -> 2624
#define SM_ES     2624        // 128 floats -> 3136
#define SM_A      4096        // up to 128 rows x 512 k fp16 = 128KB (also transpose scratch)
#define SM_W      135168      // 2 x 32768 -> 200704
#define SM_PP     135168      // 512 floats, reuses retired W region post-mainloop
#define SM_TOTAL1 200704

__device__ __forceinline__ uint32_t swz(uint32_t row, uint32_t col_bytes) {
    return row * 128u + (col_bytes ^ ((row & 7u) << 4));
}

__global__ void __launch_bounds__(256, 1) k1_gemm_scores(
    const __grid_constant__ CUtensorMap tma_w,
    const float* __restrict__ x,
    const float* __restrict__ Wsrc,
    const float* __restrict__ att_v)
{
    extern __shared__ char smem[];
    uint32_t sb = smem_u32(smem);
    const int tid = threadIdx.x, lane = tid & 31, wid = tid >> 5;

    const int cta = blockIdx.x;
    const bool big = cta < N_BIG;
    const int m0   = big ? cta * 128 : SPLIT_ROW + (cta - N_BIG) * 64;
    const int arows = big ? 128 : 64;
    const uint32_t abox = big ? 16384u : 8192u;   // per-64k-box stride in A smem

    float* vsh = (float*)(smem + SM_V);
    float* ssc = (float*)(smem + SM_SC);
    float* esh = (float*)(smem + SM_ES);

    if (tid == 0) {
        MBARRIER_INIT(sb + SM_FULL, 1);
        MBARRIER_INIT(sb + SM_FULL + 8, 1);
    }
    for (int i = tid; i < EE; i += 256) vsh[i] = att_v[i];
    if (!big && tid < 64) ssc[tid] = 0.0f;   // small path combines n-halves via atomics
    __syncthreads();

    // ---- W transpose phase: CTAs 0-63 each do one 64x64 tile ----
    if (cta < 64) {
        float* tileT = (float*)(smem + SM_A);       // scratch, pre-A-load
        const int x0 = (cta & 7) * 64, y0 = (cta >> 3) * 64;
        const int tx = tid & 63, ty = tid >> 6;     // 256 thr: ty in 0..3
#pragma unroll
        for (int i = 0; i < 64; i += 4)
            tileT[(ty + i) * 65 + tx] = Wsrc[(size_t)(y0 + ty + i) * EE + x0 + tx];
        __syncthreads();
#pragma unroll
        for (int i = 0; i < 64; i += 4)
            g_Whf[(size_t)(x0 + ty + i) * DD + y0 + tx] = __float2half(tileT[tx * 65 + ty + i]);
        FENCE_PROXY_ASYNC();   // generic writes -> async(TMA)-proxy visibility
        __threadfence();       // device-scope visibility before the arrival
        __syncthreads();
        if (tid == 0) atomicAdd(&g_wdone, 1u);
    }

    // load + convert A tile: x[m0:m0+arows, 0:512] fp32 -> fp16 SW128 smem
    {
        const float4* xg = (const float4*)(x + (size_t)m0 * DD);
        const int nload = arows * 128;   // float4 elements
#pragma unroll 8
        for (int idx = tid; idx < nload; idx += 256) {
            int r = idx >> 7, c4 = idx & 127;
            float4 f = xg[(size_t)r * 128 + c4];
            __half2 lo = __floats2half2_rn(f.x, f.y);
            __half2 hi = __floats2half2_rn(f.z, f.w);
            int k = c4 * 4;
            uint32_t off = (uint32_t)SM_A + (uint32_t)(k >> 6) * abox + swz((uint32_t)r, (k & 63) * 2);
            uint2 u;
            u.x = *reinterpret_cast<uint32_t*>(&lo);
            u.y = *reinterpret_cast<uint32_t*>(&hi);
            *reinterpret_cast<uint2*>(smem + off) = u;
        }
    }
    __syncthreads();

    // ---- EVERY CTA: wait for transpose completion, then issue W TMA 0,1 ----
    if (tid == 0) {
        unsigned v;
        do {
            asm volatile("ld.global.acquire.gpu.u32 %0, [%1];"
                         : "=r"(v) : "l"(&g_wdone));
            if (v < 64u) __nanosleep(64);
        } while (v < 64u);
        FENCE_PROXY_ASYNC();   // order the observed writes before async-proxy reads
#pragma unroll
        for (int s = 0; s < 2; s++) {
            MBARRIER_EXPECT_TX(sb + SM_FULL + 8 * s, W_CHUNK_BYTES);
#pragma unroll
            for (int kb = 0; kb < 8; kb++)
                TMA_LOAD_2D(sb + SM_W + s * W_CHUNK_BYTES + kb * 4096, &tma_w,
                            kb * 64, s * N_CHUNK, sb + SM_FULL + 8 * s);
        }
    }

    // ---- pull this warp's A fragments into registers (whole K=512) ----
    // big: warp owns rows [16*wid, +16); small: rows [16*(wid&3), +16)
    uint32_t areg[8][4][4];
    {
        uint32_t mrow0 = big ? (uint32_t)wid * 16 : (uint32_t)(wid & 3) * 16;
        uint32_t row   = mrow0 + (lane & 15);
        uint32_t abase = sb + SM_A + row * 128u;
        uint32_t axor  = ((row & 7u) << 4) ^ ((uint32_t)(lane >> 4) << 4);
#pragma unroll
        for (int kb = 0; kb < 8; kb++)
#pragma unroll
            for (int kq = 0; kq < 4; kq++)
                ldsm_x4(areg[kb][kq], abase + (uint32_t)kb * abox + (((uint32_t)kq * 32u) ^ axor));
    }

    // B ldmatrix address pieces (x4 covers 16 n-rows x k16)
    const int wn = wid >> 2;  // small path's n-half
    uint32_t nrow_lo = (lane & 7u) + (((uint32_t)lane >> 4) << 3);
    uint32_t brow = (big ? 0u : (uint32_t)wn * 2048u) + nrow_lo * 128u;
    uint32_t bxor = ((((uint32_t)lane >> 3) & 1u) << 4) ^ ((nrow_lo & 7u) << 4);

    float score0 = 0.f, score1 = 0.f;

    for (int chunk = 0; chunk < N_CHUNKS; chunk++) {
        const int buf = chunk & 1;
        const int ph  = (chunk >> 1) & 1;
        const uint32_t wb = sb + SM_W + buf * W_CHUNK_BYTES;

        MBARRIER_WAIT_PARITY(sb + SM_FULL + 8 * buf, ph);

        float acc[4][4];
#pragma unroll
        for (int g = 0; g < 4; g++)
#pragma unroll
            for (int j = 0; j < 4; j++) acc[g][j] = 0.f;

        if (big) {
#pragma unroll
            for (int kb = 0; kb < 8; kb++) {
                const uint32_t wkb = wb + (uint32_t)kb * 4096u + brow;
#pragma unroll
                for (int kq = 0; kq < 4; kq++) {
                    const uint32_t kc = (uint32_t)kq * 32u;
                    uint32_t b0[4], b1[4];
                    ldsm_x4(b0, wkb + (kc ^ bxor));
                    ldsm_x4(b1, wkb + 2048u + (kc ^ bxor));
                    mma_f16f32(acc[0], areg[kb][kq], b0);
                    mma_f16f32(acc[1], areg[kb][kq], b0 + 2);
                    mma_f16f32(acc[2], areg[kb][kq], b1);
                    mma_f16f32(acc[3], areg[kb][kq], b1 + 2);
                }
            }
        } else {
#pragma unroll
            for (int kb = 0; kb < 8; kb++) {
                const uint32_t wkb = wb + (uint32_t)kb * 4096u + brow;
#pragma unroll
                for (int kq = 0; kq < 4; kq++) {
                    const uint32_t kc = (uint32_t)kq * 32u;
                    uint32_t b0[4];
                    ldsm_x4(b0, wkb + (kc ^ bxor));
                    mma_f16f32(acc[0], areg[kb][kq], b0);
                    mma_f16f32(acc[1], areg[kb][kq], b0 + 2);
                }
            }
        }

        __syncthreads();  // all warps done reading this W buffer
        if (chunk + 2 < N_CHUNKS && tid == 0) {
            MBARRIER_EXPECT_TX(sb + SM_FULL + 8 * buf, W_CHUNK_BYTES);
#pragma unroll
            for (int kb = 0; kb < 8; kb++)
                TMA_LOAD_2D(wb + kb * 4096, &tma_w,
                            kb * 64, (chunk + 2) * N_CHUNK, sb + SM_FULL + 8 * buf);
        }

        // epilogue after prefetch: tanh + dot with v
        if (big) {
            const int jb = chunk * N_CHUNK + (lane & 3) * 2;
#pragma unroll
            for (int g = 0; g < 4; g++) {
                float v0 = vsh[jb + g * 8];
                float v1 = vsh[jb + g * 8 + 1];
                score0 += tanh_approx(acc[g][0]) * v0 + tanh_approx(acc[g][1]) * v1;
                score1 += tanh_approx(acc[g][2]) * v0 + tanh_approx(acc[g][3]) * v1;
            }
        } else {
            const int jb = chunk * N_CHUNK + wn * 16 + (lane & 3) * 2;
#pragma unroll
            for (int g = 0; g < 2; g++) {
                float v0 = vsh[jb + g * 8];
                float v1 = vsh[jb + g * 8 + 1];
                score0 += tanh_approx(acc[g][0]) * v0 + tanh_approx(acc[g][1]) * v1;
                score1 += tanh_approx(acc[g][2]) * v0 + tanh_approx(acc[g][3]) * v1;
            }
        }
    }

    // reduce over n within warp: lanes sharing a row differ only in (lane&3)
    score0 += __shfl_xor_sync(0xFFFFFFFF, score0, 1);
    score0 += __shfl_xor_sync(0xFFFFFFFF, score0, 2);
    score1 += __shfl_xor_sync(0xFFFFFFFF, score1, 1);
    score1 += __shfl_xor_sync(0xFFFFFFFF, score1, 2);
    if (big) {
        if ((lane & 3) == 0) {
            int r = wid * 16 + (lane >> 2);
            ssc[r]     = score0;
            ssc[r + 8] = score1;
        }
    } else {
        if ((lane & 3) == 0) {   // combine n-halves (ssc pre-zeroed)
            int r = (wid & 3) * 16 + (lane >> 2);
            atomicAdd(&ssc[r],     score0);
            atomicAdd(&ssc[r + 8], score1);
        }
    }
    __syncthreads();

    // ---- online-softmax pooling partials for this CTA's rows ----
    float m_c = -1e30f;
    for (int t = 0; t < arows; t++) m_c = fmaxf(m_c, ssc[t]);
    if (tid < arows) esh[tid] = __expf(ssc[tid] - m_c);
    __syncthreads();

    if (wid == 0) {  // sum of exps + stats store
        float s = 0.f;
        for (int t = lane; t < arows; t += 32) s += esh[t];
        s += __shfl_xor_sync(0xFFFFFFFF, s, 16);
        s += __shfl_xor_sync(0xFFFFFFFF, s, 8);
        s += __shfl_xor_sync(0xFFFFFFFF, s, 4);
        s += __shfl_xor_sync(0xFFFFFFFF, s, 2);
        s += __shfl_xor_sync(0xFFFFFFFF, s, 1);
        if (lane == 0) { g_pmax[cta] = m_c; g_psum[cta] = s; }
    }

    // partial weighted sum from the fp16 A tile in SMEM.
    // dg = tid&127 owns d [4*dg,+4); half = tid>>7 owns rows [half*arows/2, +arows/2)
    {
        const int dg = tid & 127, half = tid >> 7;
        const int hrows = arows >> 1;
        const uint32_t pbase = (uint32_t)SM_A + ((uint32_t)dg >> 4) * abox;
        const uint32_t colb  = ((uint32_t)dg & 15u) * 8u;
        float ax = 0.f, ay = 0.f, az = 0.f, aw = 0.f;
#pragma unroll 8
        for (int i = 0; i < hrows; i++) {
            int t = half * hrows + i;
            uint2 u = *reinterpret_cast<const uint2*>(smem + pbase + swz((uint32_t)t, colb));
            float2 lo = __half22float2(*reinterpret_cast<__half2*>(&u.x));
            float2 hi = __half22float2(*reinterpret_cast<__half2*>(&u.y));
            float w = esh[t];
            ax = fmaf(w, lo.x, ax); ay = fmaf(w, lo.y, ay);
            az = fmaf(w, hi.x, az); aw = fmaf(w, hi.y, aw);
        }
        float4 o; o.x = ax; o.y = ay; o.z = az; o.w = aw;
        if (half == 1) ((float4*)(smem + SM_PP))[dg] = o;
        __syncthreads();
        if (half == 0) {
            float4 p2 = ((const float4*)(smem + SM_PP))[dg];
            o.x += p2.x; o.y += p2.y; o.z += p2.z; o.w += p2.w;
            ((float4*)(g_part + (size_t)cta * DD))[dg] = o;
        }
    }
}

// ---------------- kernel 2: combine per-CTA partials -> out ------------------
// grid BB, 512 threads; thread owns one d. Batch b<13: 32 big-tile partials;
// b>=13: 64 small-tile partials.
__global__ void __launch_bounds__(512) k2_combine(float* __restrict__ out) {
    __shared__ float fm[64], fc[64];
    __shared__ float denom_s;
    const int b = blockIdx.x, tid = threadIdx.x;
    const int base = (b < 13) ? 32 * b : N_BIG + 64 * (b - 13);
    const int cnt  = (b < 13) ? 32 : 64;

    if (tid < cnt) fm[tid] = g_pmax[base + tid];
    __syncthreads();
    float M = -1e30f;
    for (int c = 0; c < cnt; c++) M = fmaxf(M, fm[c]);
    if (tid < cnt) fc[tid] = __expf(fm[tid] - M);
    __syncthreads();
    if (tid < 32) {
        float s = 0.f;
        for (int c = tid; c < cnt; c += 32) s += fc[c] * g_psum[base + c];
        s += __shfl_xor_sync(0xFFFFFFFF, s, 16);
        s += __shfl_xor_sync(0xFFFFFFFF, s, 8);
        s += __shfl_xor_sync(0xFFFFFFFF, s, 4);
        s += __shfl_xor_sync(0xFFFFFFFF, s, 2);
        s += __shfl_xor_sync(0xFFFFFFFF, s, 1);
        if (tid == 0) denom_s = s;
    }
    __syncthreads();

    float num = 0.f;
    for (int c = 0; c < cnt; c++)
        num += fc[c] * g_part[((size_t)(base + c)) * DD + tid];
    out[b * DD + tid] = num / denom_s;
}

// ---------------- host ----------------
typedef CUresult (*EncodeTiledFn)(
    CUtensorMap*, CUtensorMapDataType, cuuint32_t, void*,
    const cuuint64_t*, const cuuint64_t*, const cuuint32_t*, const cuuint32_t*,
    CUtensorMapInterleave, CUtensorMapSwizzle, CUtensorMapL2promotion, CUtensorMapFloatOOBfill);

extern "C" void kernel_launch(void* const* d_in, const int* in_sizes, int n_in,
                              void* d_out, int out_size) {
    const float* x = (const float*)d_in[0];
    const float* W = (const float*)d_in[1];
    const float* v = (const float*)d_in[2];
    float* out = (float*)d_out;

    EncodeTiledFn encode = nullptr;
    cudaDriverEntryPointQueryResult qres;
    cudaGetDriverEntryPointByVersion("cuTensorMapEncodeTiled", (void**)&encode,
                                     12000, cudaEnableDefault, &qres);

    void* whf_ptr = nullptr;
    cudaGetSymbolAddress(&whf_ptr, g_Whf);

    // TMA map for W: dims (k=512, n=512) fp16, box (64, 32), SW128
    CUtensorMap tma_w{};
    if (encode) {
        cuuint64_t dims[2]    = { (cuuint64_t)DD, (cuuint64_t)EE };
        cuuint64_t strides[1] = { (cuuint64_t)DD * sizeof(__half) };
        cuuint32_t box[2]     = { 64, N_CHUNK };
        cuuint32_t es[2]      = { 1, 1 };
        encode(&tma_w, CU_TENSOR_MAP_DATA_TYPE_FLOAT16, 2, whf_ptr,
               dims, strides, box, es,
               CU_TENSOR_MAP_INTERLEAVE_NONE, CU_TENSOR_MAP_SWIZZLE_128B,
               CU_TENSOR_MAP_L2_PROMOTION_L2_128B, CU_TENSOR_MAP_FLOAT_OOB_FILL_NONE);
    }

    cudaFuncSetAttribute(k1_gemm_scores, cudaFuncAttributeMaxDynamicSharedMemorySize, SM_TOTAL1);
    k1_gemm_scores<<<NCTAS, 256, SM_TOTAL1>>>(tma_w, x, W, v);

    k2_combine<<<BB, 512>>>(out);
}

// round 16
// speedup vs baseline: 1.0035x; 1.0035x over previous
#include <cuda_runtime.h>
#include <cuda.h>
#include <cuda_fp16.h>
#include <cstdint>

// Problem dims (fixed by reference)
#define BB 16
#define TT 4096
#define DD 512           // K dim of GEMM / feature dim
#define EE 512           // N dim of GEMM
#define MTOT (BB*TT)     // 65536 rows

// Mixed tile schedule: batches 0-12 -> 128-row tiles, batches 13-15 -> 64-row.
#define N_BIG   416      // 13 batches x 32 tiles
#define N_SMALL 192      // 3 batches x 64 tiles
#define NCTAS   (N_BIG + N_SMALL)   // 608
#define SPLIT_ROW (N_BIG * 128)     // 53248 = start of small-tile region

// ---------------- scratch (device globals; no allocation) ----------------
__device__ __align__(16) __half g_Whf[EE * DD];    // transposed W fp16: Whf[e][d]
__device__ __align__(16) float g_part[NCTAS * DD]; // per-CTA partial weighted sums
__device__ __align__(16) float g_pmax[NCTAS];      // per-CTA score max
__device__ __align__(16) float g_psum[NCTAS];      // per-CTA sum exp(score-max)
__device__ unsigned g_wdone;  // transpose arrival counter; NEVER reset (replay-safe)

// ---------------- PTX helpers ----------------
__device__ __forceinline__ uint32_t smem_u32(const void* p) {
    uint32_t a;
    asm("{ .reg .u64 t; cvta.to.shared.u64 t, %1; cvt.u32.u64 %0, t; }" : "=r"(a) : "l"(p));
    return a;
}

#define MBARRIER_INIT(addr, cnt) \
    asm volatile("mbarrier.init.shared.b64 [%0], %1;" :: "r"((uint32_t)(addr)), "r"((uint32_t)(cnt)) : "memory")

#define MBARRIER_EXPECT_TX(addr, bytes) \
    asm volatile("mbarrier.arrive.expect_tx.shared.b64 _, [%0], %1;" :: "r"((uint32_t)(addr)), "r"((uint32_t)(bytes)) : "memory")

#define MBARRIER_WAIT_PARITY(mbar_smem_addr, phase_parity) do { \
    uint32_t _mbar = (uint32_t)(mbar_smem_addr); \
    uint32_t _parity = (uint32_t)(phase_parity); \
    uint32_t _done; \
    asm volatile( \
        "{\n\t" \
        ".reg .pred p;\n\t" \
        "mbarrier.try_wait.parity.acquire.cta.shared::cta.b64 p, [%1], %2;\n\t" \
        "selp.b32 %0, 1, 0, p;\n\t" \
        "}" \
        : "=r"(_done) : "r"(_mbar), "r"(_parity) : "memory"); \
    if (!_done) { \
        asm volatile( \
            "{\n\t" \
            ".reg .pred P1;\n\t" \
            "WAIT_LOOP_%=:\n\t" \
            "mbarrier.try_wait.parity.acquire.cta.shared::cta.b64 P1, [%0], %1, 0x989680;\n\t" \
            "@P1 bra.uni WAIT_DONE_%=;\n\t" \
            "bra.uni WAIT_LOOP_%=;\n\t" \
            "WAIT_DONE_%=:\n\t" \
            "}" \
            :: "r"(_mbar), "r"(_parity) : "memory"); \
    } \
} while(0)

#define TMA_LOAD_2D(smem_addr, map_ptr, c0, c1, mbar) \
    asm volatile("cp.async.bulk.tensor.2d.shared::cta.global.tile.mbarrier::complete_tx::bytes " \
        "[%0], [%1, {%2, %3}], [%4];" \
        :: "r"((uint32_t)(smem_addr)), "l"(map_ptr), "r"((int)(c0)), "r"((int)(c1)), \
           "r"((uint32_t)(mbar)) : "memory")

#define FENCE_PROXY_ASYNC() asm volatile("fence.proxy.async;" ::: "memory")

__device__ __forceinline__ void ldsm_x4(uint32_t* r, uint32_t addr) {
    asm volatile("ldmatrix.sync.aligned.m8n8.x4.shared.b16 {%0,%1,%2,%3}, [%4];"
        : "=r"(r[0]), "=r"(r[1]), "=r"(r[2]), "=r"(r[3]) : "r"(addr));
}
// fp16 inputs, fp32 accumulate
__device__ __forceinline__ void mma_f16f32(float* d, const uint32_t* a, const uint32_t* b) {
    asm volatile("mma.sync.aligned.m16n8k16.row.col.f32.f16.f16.f32 "
        "{%0,%1,%2,%3}, {%4,%5,%6,%7}, {%8,%9}, {%0,%1,%2,%3};"
        : "+f"(d[0]), "+f"(d[1]), "+f"(d[2]), "+f"(d[3])
        : "r"(a[0]), "r"(a[1]), "r"(a[2]), "r"(a[3]), "r"(b[0]), "r"(b[1]));
}
__device__ __forceinline__ float tanh_approx(float x) {
    float r;
    asm("tanh.approx.f32 %0, %1;" : "=f"(r) : "f"(x));
    return r;
}

// ---------------- kernel 1: transpose(W) + GEMM + tanh + dot(v) + pool ------
// (byte-identical logic to R15 — proven at 129.5us with k1 ~= 119.4us)
#define N_CHUNK  32
#define N_CHUNKS 16
#define W_CHUNK_BYTES 32768   // 32 n-rows x 512 k x 2B

// smem offsets
#define SM_FULL   0           // 2 full mbarriers
#define SM_V      64          // 512 floats -> 2112
#define SM_SC     2112        // 128 floats -> 2624
#define SM_ES     2624        // 128 floats -> 3136
#define SM_A      4096        // up to 128 rows x 512 k fp16 = 128KB (also transpose scratch)
#define SM_W      135168      // 2 x 32768 -> 200704
#define SM_PP     135168      // 512 floats, reuses retired W region post-mainloop
#define SM_TOTAL1 200704

__device__ __forceinline__ uint32_t swz(uint32_t row, uint32_t col_bytes) {
    return row * 128u + (col_bytes ^ ((row & 7u) << 4));
}

__global__ void __launch_bounds__(256, 1) k1_gemm_scores(
    const __grid_constant__ CUtensorMap tma_w,
    const float* __restrict__ x,
    const float* __restrict__ Wsrc,
    const float* __restrict__ att_v)
{
    extern __shared__ char smem[];
    uint32_t sb = smem_u32(smem);
    const int tid = threadIdx.x, lane = tid & 31, wid = tid >> 5;

    const int cta = blockIdx.x;
    const bool big = cta < N_BIG;
    const int m0   = big ? cta * 128 : SPLIT_ROW + (cta - N_BIG) * 64;
    const int arows = big ? 128 : 64;
    const uint32_t abox = big ? 16384u : 8192u;   // per-64k-box stride in A smem

    float* vsh = (float*)(smem + SM_V);
    float* ssc = (float*)(smem + SM_SC);
    float* esh = (float*)(smem + SM_ES);

    if (tid == 0) {
        MBARRIER_INIT(sb + SM_FULL, 1);
        MBARRIER_INIT(sb + SM_FULL + 8, 1);
    }
    for (int i = tid; i < EE; i += 256) vsh[i] = att_v[i];
    if (!big && tid < 64) ssc[tid] = 0.0f;   // small path combines n-halves via atomics
    __syncthreads();

    // ---- W transpose phase: CTAs 0-63 each do one 64x64 tile ----
    if (cta < 64) {
        float* tileT = (float*)(smem + SM_A);       // scratch, pre-A-load
        const int x0 = (cta & 7) * 64, y0 = (cta >> 3) * 64;
        const int tx = tid & 63, ty = tid >> 6;     // 256 thr: ty in 0..3
#pragma unroll
        for (int i = 0; i < 64; i += 4)
            tileT[(ty + i) * 65 + tx] = Wsrc[(size_t)(y0 + ty + i) * EE + x0 + tx];
        __syncthreads();
#pragma unroll
        for (int i = 0; i < 64; i += 4)
            g_Whf[(size_t)(x0 + ty + i) * DD + y0 + tx] = __float2half(tileT[tx * 65 + ty + i]);
        FENCE_PROXY_ASYNC();   // generic writes -> async(TMA)-proxy visibility
        __threadfence();       // device-scope visibility before the arrival
        __syncthreads();
        if (tid == 0) atomicAdd(&g_wdone, 1u);
    }

    // load + convert A tile: x[m0:m0+arows, 0:512] fp32 -> fp16 SW128 smem
    {
        const float4* xg = (const float4*)(x + (size_t)m0 * DD);
        const int nload = arows * 128;   // float4 elements
#pragma unroll 8
        for (int idx = tid; idx < nload; idx += 256) {
            int r = idx >> 7, c4 = idx & 127;
            float4 f = xg[(size_t)r * 128 + c4];
            __half2 lo = __floats2half2_rn(f.x, f.y);
            __half2 hi = __floats2half2_rn(f.z, f.w);
            int k = c4 * 4;
            uint32_t off = (uint32_t)SM_A + (uint32_t)(k >> 6) * abox + swz((uint32_t)r, (k & 63) * 2);
            uint2 u;
            u.x = *reinterpret_cast<uint32_t*>(&lo);
            u.y = *reinterpret_cast<uint32_t*>(&hi);
            *reinterpret_cast<uint2*>(smem + off) = u;
        }
    }
    __syncthreads();

    // ---- EVERY CTA: wait for transpose completion, then issue W TMA 0,1 ----
    if (tid == 0) {
        unsigned v;
        do {
            asm volatile("ld.global.acquire.gpu.u32 %0, [%1];"
                         : "=r"(v) : "l"(&g_wdone));
            if (v < 64u) __nanosleep(64);
        } while (v < 64u);
        FENCE_PROXY_ASYNC();   // order the observed writes before async-proxy reads
#pragma unroll
        for (int s = 0; s < 2; s++) {
            MBARRIER_EXPECT_TX(sb + SM_FULL + 8 * s, W_CHUNK_BYTES);
#pragma unroll
            for (int kb = 0; kb < 8; kb++)
                TMA_LOAD_2D(sb + SM_W + s * W_CHUNK_BYTES + kb * 4096, &tma_w,
                            kb * 64, s * N_CHUNK, sb + SM_FULL + 8 * s);
        }
    }

    // ---- pull this warp's A fragments into registers (whole K=512) ----
    uint32_t areg[8][4][4];
    {
        uint32_t mrow0 = big ? (uint32_t)wid * 16 : (uint32_t)(wid & 3) * 16;
        uint32_t row   = mrow0 + (lane & 15);
        uint32_t abase = sb + SM_A + row * 128u;
        uint32_t axor  = ((row & 7u) << 4) ^ ((uint32_t)(lane >> 4) << 4);
#pragma unroll
        for (int kb = 0; kb < 8; kb++)
#pragma unroll
            for (int kq = 0; kq < 4; kq++)
                ldsm_x4(areg[kb][kq], abase + (uint32_t)kb * abox + (((uint32_t)kq * 32u) ^ axor));
    }

    // B ldmatrix address pieces (x4 covers 16 n-rows x k16)
    const int wn = wid >> 2;  // small path's n-half
    uint32_t nrow_lo = (lane & 7u) + (((uint32_t)lane >> 4) << 3);
    uint32_t brow = (big ? 0u : (uint32_t)wn * 2048u) + nrow_lo * 128u;
    uint32_t bxor = ((((uint32_t)lane >> 3) & 1u) << 4) ^ ((nrow_lo & 7u) << 4);

    float score0 = 0.f, score1 = 0.f;

    for (int chunk = 0; chunk < N_CHUNKS; chunk++) {
        const int buf = chunk & 1;
        const int ph  = (chunk >> 1) & 1;
        const uint32_t wb = sb + SM_W + buf * W_CHUNK_BYTES;

        MBARRIER_WAIT_PARITY(sb + SM_FULL + 8 * buf, ph);

        float acc[4][4];
#pragma unroll
        for (int g = 0; g < 4; g++)
#pragma unroll
            for (int j = 0; j < 4; j++) acc[g][j] = 0.f;

        if (big) {
#pragma unroll
            for (int kb = 0; kb < 8; kb++) {
                const uint32_t wkb = wb + (uint32_t)kb * 4096u + brow;
#pragma unroll
                for (int kq = 0; kq < 4; kq++) {
                    const uint32_t kc = (uint32_t)kq * 32u;
                    uint32_t b0[4], b1[4];
                    ldsm_x4(b0, wkb + (kc ^ bxor));
                    ldsm_x4(b1, wkb + 2048u + (kc ^ bxor));
                    mma_f16f32(acc[0], areg[kb][kq], b0);
                    mma_f16f32(acc[1], areg[kb][kq], b0 + 2);
                    mma_f16f32(acc[2], areg[kb][kq], b1);
                    mma_f16f32(acc[3], areg[kb][kq], b1 + 2);
                }
            }
        } else {
#pragma unroll
            for (int kb = 0; kb < 8; kb++) {
                const uint32_t wkb = wb + (uint32_t)kb * 4096u + brow;
#pragma unroll
                for (int kq = 0; kq < 4; kq++) {
                    const uint32_t kc = (uint32_t)kq * 32u;
                    uint32_t b0[4];
                    ldsm_x4(b0, wkb + (kc ^ bxor));
                    mma_f16f32(acc[0], areg[kb][kq], b0);
                    mma_f16f32(acc[1], areg[kb][kq], b0 + 2);
                }
            }
        }

        __syncthreads();  // all warps done reading this W buffer
        if (chunk + 2 < N_CHUNKS && tid == 0) {
            MBARRIER_EXPECT_TX(sb + SM_FULL + 8 * buf, W_CHUNK_BYTES);
#pragma unroll
            for (int kb = 0; kb < 8; kb++)
                TMA_LOAD_2D(wb + kb * 4096, &tma_w,
                            kb * 64, (chunk + 2) * N_CHUNK, sb + SM_FULL + 8 * buf);
        }

        // epilogue after prefetch: tanh + dot with v
        if (big) {
            const int jb = chunk * N_CHUNK + (lane & 3) * 2;
#pragma unroll
            for (int g = 0; g < 4; g++) {
                float v0 = vsh[jb + g * 8];
                float v1 = vsh[jb + g * 8 + 1];
                score0 += tanh_approx(acc[g][0]) * v0 + tanh_approx(acc[g][1]) * v1;
                score1 += tanh_approx(acc[g][2]) * v0 + tanh_approx(acc[g][3]) * v1;
            }
        } else {
            const int jb = chunk * N_CHUNK + wn * 16 + (lane & 3) * 2;
#pragma unroll
            for (int g = 0; g < 2; g++) {
                float v0 = vsh[jb + g * 8];
                float v1 = vsh[jb + g * 8 + 1];
                score0 += tanh_approx(acc[g][0]) * v0 + tanh_approx(acc[g][1]) * v1;
                score1 += tanh_approx(acc[g][2]) * v0 + tanh_approx(acc[g][3]) * v1;
            }
        }
    }

    // reduce over n within warp: lanes sharing a row differ only in (lane&3)
    score0 += __shfl_xor_sync(0xFFFFFFFF, score0, 1);
    score0 += __shfl_xor_sync(0xFFFFFFFF, score0, 2);
    score1 += __shfl_xor_sync(0xFFFFFFFF, score1, 1);
    score1 += __shfl_xor_sync(0xFFFFFFFF, score1, 2);
    if (big) {
        if ((lane & 3) == 0) {
            int r = wid * 16 + (lane >> 2);
            ssc[r]     = score0;
            ssc[r + 8] = score1;
        }
    } else {
        if ((lane & 3) == 0) {   // combine n-halves (ssc pre-zeroed)
            int r = (wid & 3) * 16 + (lane >> 2);
            atomicAdd(&ssc[r],     score0);
            atomicAdd(&ssc[r + 8], score1);
        }
    }
    __syncthreads();

    // ---- online-softmax pooling partials for this CTA's rows ----
    float m_c = -1e30f;
    for (int t = 0; t < arows; t++) m_c = fmaxf(m_c, ssc[t]);
    if (tid < arows) esh[tid] = __expf(ssc[tid] - m_c);
    __syncthreads();

    if (wid == 0) {  // sum of exps + stats store
        float s = 0.f;
        for (int t = lane; t < arows; t += 32) s += esh[t];
        s += __shfl_xor_sync(0xFFFFFFFF, s, 16);
        s += __shfl_xor_sync(0xFFFFFFFF, s, 8);
        s += __shfl_xor_sync(0xFFFFFFFF, s, 4);
        s += __shfl_xor_sync(0xFFFFFFFF, s, 2);
        s += __shfl_xor_sync(0xFFFFFFFF, s, 1);
        if (lane == 0) { g_pmax[cta] = m_c; g_psum[cta] = s; }
    }

    // partial weighted sum from the fp16 A tile in SMEM.
    {
        const int dg = tid & 127, half = tid >> 7;
        const int hrows = arows >> 1;
        const uint32_t pbase = (uint32_t)SM_A + ((uint32_t)dg >> 4) * abox;
        const uint32_t colb  = ((uint32_t)dg & 15u) * 8u;
        float ax = 0.f, ay = 0.f, az = 0.f, aw = 0.f;
#pragma unroll 8
        for (int i = 0; i < hrows; i++) {
            int t = half * hrows + i;
            uint2 u = *reinterpret_cast<const uint2*>(smem + pbase + swz((uint32_t)t, colb));
            float2 lo = __half22float2(*reinterpret_cast<__half2*>(&u.x));
            float2 hi = __half22float2(*reinterpret_cast<__half2*>(&u.y));
            float w = esh[t];
            ax = fmaf(w, lo.x, ax); ay = fmaf(w, lo.y, ay);
            az = fmaf(w, hi.x, az); aw = fmaf(w, hi.y, aw);
        }
        float4 o; o.x = ax; o.y = ay; o.z = az; o.w = aw;
        if (half == 1) ((float4*)(smem + SM_PP))[dg] = o;
        __syncthreads();
        if (half == 0) {
            float4 p2 = ((const float4*)(smem + SM_PP))[dg];
            o.x += p2.x; o.y += p2.y; o.z += p2.z; o.w += p2.w;
            ((float4*)(g_part + (size_t)cta * DD))[dg] = o;
        }
    }
}

// ---------------- kernel 2: combine per-CTA partials -> out ------------------
// grid (BB, K2_SPLIT), 512 threads; thread owns one d. Each block sums a
// slice of the batch's partials (8 or 16), scales by 1/denom (computed
// redundantly per block — two cheap coalesced loads), atomicAdds into the
// zeroed out buffer. 64 blocks spread over 64 SMs; unrolled loads give MLP.
#define K2_SPLIT 4
__global__ void __launch_bounds__(512) k2_combine(float* __restrict__ out) {
    __shared__ float fm[64], fc[64];
    __shared__ float denom_s;
    const int b = blockIdx.x, j = blockIdx.y, tid = threadIdx.x;
    const int base = (b < 13) ? 32 * b : N_BIG + 64 * (b - 13);
    const int cnt  = (b < 13) ? 32 : 64;
    const int slice = cnt / K2_SPLIT;      // 8 or 16
    const int c0 = j * slice;

    if (tid < cnt) fm[tid] = g_pmax[base + tid];
    __syncthreads();
    float M = -1e30f;
    for (int c = 0; c < cnt; c++) M = fmaxf(M, fm[c]);
    if (tid < cnt) fc[tid] = __expf(fm[tid] - M);
    __syncthreads();
    if (tid < 32) {
        float s = 0.f;
        for (int c = tid; c < cnt; c += 32) s += fc[c] * g_psum[base + c];
        s += __shfl_xor_sync(0xFFFFFFFF, s, 16);
        s += __shfl_xor_sync(0xFFFFFFFF, s, 8);
        s += __shfl_xor_sync(0xFFFFFFFF, s, 4);
        s += __shfl_xor_sync(0xFFFFFFFF, s, 2);
        s += __shfl_xor_sync(0xFFFFFFFF, s, 1);
        if (tid == 0) denom_s = s;
    }
    __syncthreads();
    const float inv = 1.0f / denom_s;

    float num = 0.f;
#pragma unroll 8
    for (int i = 0; i < slice; i++)
        num += fc[c0 + i] * g_part[((size_t)(base + c0 + i)) * DD + tid];
    atomicAdd(&out[b * DD + tid], num * inv);
}

// ---------------- host ----------------
typedef CUresult (*EncodeTiledFn)(
    CUtensorMap*, CUtensorMapDataType, cuuint32_t, void*,
    const cuuint64_t*, const cuuint64_t*, const cuuint32_t*, const cuuint32_t*,
    CUtensorMapInterleave, CUtensorMapSwizzle, CUtensorMapL2promotion, CUtensorMapFloatOOBfill);

extern "C" void kernel_launch(void* const* d_in, const int* in_sizes, int n_in,
                              void* d_out, int out_size) {
    const float* x = (const float*)d_in[0];
    const float* W = (const float*)d_in[1];
    const float* v = (const float*)d_in[2];
    float* out = (float*)d_out;

    EncodeTiledFn encode = nullptr;
    cudaDriverEntryPointQueryResult qres;
    cudaGetDriverEntryPointByVersion("cuTensorMapEncodeTiled", (void**)&encode,
                                     12000, cudaEnableDefault, &qres);

    void* whf_ptr = nullptr;
    cudaGetSymbolAddress(&whf_ptr, g_Whf);

    // TMA map for W: dims (k=512, n=512) fp16, box (64, 32), SW128
    CUtensorMap tma_w{};
    if (encode) {
        cuuint64_t dims[2]    = { (cuuint64_t)DD, (cuuint64_t)EE };
        cuuint64_t strides[1] = { (cuuint64_t)DD * sizeof(__half) };
        cuuint32_t box[2]     = { 64, N_CHUNK };
        cuuint32_t es[2]      = { 1, 1 };
        encode(&tma_w, CU_TENSOR_MAP_DATA_TYPE_FLOAT16, 2, whf_ptr,
               dims, strides, box, es,
               CU_TENSOR_MAP_INTERLEAVE_NONE, CU_TENSOR_MAP_SWIZZLE_128B,
               CU_TENSOR_MAP_L2_PROMOTION_L2_128B, CU_TENSOR_MAP_FLOAT_OOB_FILL_NONE);
    }

    cudaFuncSetAttribute(k1_gemm_scores, cudaFuncAttributeMaxDynamicSharedMemorySize, SM_TOTAL1);
    k1_gemm_scores<<<NCTAS, 256, SM_TOTAL1>>>(tma_w, x, W, v);

    cudaMemsetAsync(d_out, 0, (size_t)out_size * sizeof(float));
    k2_combine<<<dim3(BB, K2_SPLIT), 512>>>(out);
}